// round 16
// baseline (speedup 1.0000x reference)
#include <cuda_runtime.h>
#include <cuda_bf16.h>

#define BB 8
#define CC 256
#define HW 1024
#define HEADS 8
#define HD 32
#define NG 8
#define GS 32

__device__ __align__(256) __nv_bfloat16 g_hh[BB * CC * HW];
__device__ __align__(256) __nv_bfloat16 g_qkvh[BB * 3 * CC * HW];
__device__ __align__(256) __nv_bfloat16 g_aoh[BB * CC * HW];
__device__ __align__(256) __nv_bfloat16 g_wqh[3 * CC * CC];
__device__ __align__(256) __nv_bfloat16 g_woh[CC * CC];

// ---------------------------------------------------------------------------
__device__ __forceinline__ void mma_bf16(float c[4], unsigned a0, unsigned a1,
                                         unsigned a2, unsigned a3,
                                         unsigned b0, unsigned b1) {
    asm volatile(
        "mma.sync.aligned.m16n8k16.row.col.f32.bf16.bf16.f32 "
        "{%0,%1,%2,%3},{%4,%5,%6,%7},{%8,%9},{%0,%1,%2,%3};"
        : "+f"(c[0]), "+f"(c[1]), "+f"(c[2]), "+f"(c[3])
        : "r"(a0), "r"(a1), "r"(a2), "r"(a3), "r"(b0), "r"(b1));
}

__device__ __forceinline__ void mma_bf16_z(float c[4], unsigned a0, unsigned a1,
                                           unsigned a2, unsigned a3,
                                           unsigned b0, unsigned b1) {
    asm volatile(
        "mma.sync.aligned.m16n8k16.row.col.f32.bf16.bf16.f32 "
        "{%0,%1,%2,%3},{%4,%5,%6,%7},{%8,%9},{%10,%11,%12,%13};"
        : "=f"(c[0]), "=f"(c[1]), "=f"(c[2]), "=f"(c[3])
        : "r"(a0), "r"(a1), "r"(a2), "r"(a3), "r"(b0), "r"(b1),
          "f"(0.f), "f"(0.f), "f"(0.f), "f"(0.f));
}

__device__ __forceinline__ float ex2(float x) {
    float r;
    asm("ex2.approx.f32 %0, %1;" : "=f"(r) : "f"(x));
    return r;
}

__device__ __forceinline__ unsigned pack_bf16(float lo, float hi) {
    __nv_bfloat162 t = __floats2bfloat162_rn(lo, hi);
    return *(unsigned*)&t;
}

__device__ __forceinline__ void cp16(void* smem, const void* gmem) {
    unsigned s = (unsigned)__cvta_generic_to_shared(smem);
    asm volatile("cp.async.ca.shared.global [%0], [%1], 16;" :: "r"(s), "l"(gmem));
}

__device__ __forceinline__ void ldsm_x4(unsigned& r0, unsigned& r1, unsigned& r2,
                                        unsigned& r3, unsigned addr) {
    asm volatile("ldmatrix.sync.aligned.m8n8.x4.shared.b16 {%0,%1,%2,%3}, [%4];"
                 : "=r"(r0), "=r"(r1), "=r"(r2), "=r"(r3) : "r"(addr));
}

__device__ __forceinline__ void ldsm_x4_t(unsigned& r0, unsigned& r1, unsigned& r2,
                                          unsigned& r3, unsigned addr) {
    asm volatile("ldmatrix.sync.aligned.m8n8.x4.trans.shared.b16 {%0,%1,%2,%3}, [%4];"
                 : "=r"(r0), "=r"(r1), "=r"(r2), "=r"(r3) : "r"(addr));
}

// ---------------------------------------------------------------------------
// Kernel 1: GroupNorm + weight conversion (fused, validated)
// ---------------------------------------------------------------------------
__global__ __launch_bounds__(256) void gn_wconv_kernel(const float* __restrict__ x,
                                                       const float* __restrict__ sc,
                                                       const float* __restrict__ bi,
                                                       const float* __restrict__ wq,
                                                       const float* __restrict__ wo) {
    if (blockIdx.x >= BB * NG) {
        const int i = (blockIdx.x - BB * NG) * 256 + threadIdx.x;
        if (i < 49152) {
            float4 v = ((const float4*)wq)[i];
            uint2 o; o.x = pack_bf16(v.x, v.y); o.y = pack_bf16(v.z, v.w);
            ((uint2*)g_wqh)[i] = o;
        } else {
            const int k = i - 49152;
            float4 v = ((const float4*)wo)[k];
            uint2 o; o.x = pack_bf16(v.x, v.y); o.y = pack_bf16(v.z, v.w);
            ((uint2*)g_woh)[k] = o;
        }
        return;
    }
    const int b = blockIdx.x / NG;
    const int g = blockIdx.x % NG;
    const int NE = GS * HW;
    const float* xp = x + ((size_t)b * CC + g * GS) * HW;
    __nv_bfloat16* hp = g_hh + ((size_t)b * CC + g * GS) * HW;

    float s = 0.f, s2 = 0.f;
    const float4* x4 = (const float4*)xp;
    for (int i = threadIdx.x; i < NE / 4; i += 256) {
        float4 v = x4[i];
        s += v.x + v.y + v.z + v.w;
        s2 += v.x * v.x + v.y * v.y + v.z * v.z + v.w * v.w;
    }
    __shared__ float rs[256], rs2[256];
    rs[threadIdx.x] = s; rs2[threadIdx.x] = s2;
    __syncthreads();
    for (int o = 128; o > 0; o >>= 1) {
        if (threadIdx.x < o) {
            rs[threadIdx.x] += rs[threadIdx.x + o];
            rs2[threadIdx.x] += rs2[threadIdx.x + o];
        }
        __syncthreads();
    }
    const float mean = rs[0] / NE;
    const float var = rs2[0] / NE - mean * mean;
    const float rstd = rsqrtf(var + 1e-5f);

    uint2* h2 = (uint2*)hp;
    for (int i = threadIdx.x; i < NE / 4; i += 256) {
        const int c = g * GS + (i >> 8);
        const float a = sc[c] * rstd;
        const float d = bi[c] - mean * a;
        float4 v = x4[i];
        uint2 o;
        o.x = pack_bf16(v.x * a + d, v.y * a + d);
        o.y = pack_bf16(v.z * a + d, v.w * a + d);
        h2[i] = o;
    }
}

// ---------------------------------------------------------------------------
// Kernel 2/4: bf16 m16n8k16 GEMM, 128 x NT tile (NT = 128 or 64).
// NT=128: warps 4m x 2n (32x64). NT=64: warps 4m x 2n (32x32), B loader
// uses threads < 128 only (total B staging work unchanged vs NT=128).
// ---------------------------------------------------------------------------
template <int NT, int M_TOTAL, bool RESID, bool OBF16>
__global__ __launch_bounds__(256, 2) void gemm_bf(const __nv_bfloat16* __restrict__ A,
                                                  const float* __restrict__ bias,
                                                  const __nv_bfloat16* __restrict__ Bmat,
                                                  const float* __restrict__ resid,
                                                  void* __restrict__ Cout_v) {
    const int bb = blockIdx.z;
    const int m0 = blockIdx.y * 128;
    const int n0 = blockIdx.x * NT;
    const __nv_bfloat16* Bp = Bmat + (size_t)bb * CC * HW;
    const float* Rp = RESID ? (resid + (size_t)bb * M_TOTAL * HW) : nullptr;

    __shared__ __align__(128) __nv_bfloat16 As[2][128 * 40];
    __shared__ __align__(128) __nv_bfloat16 Bt[2][NT * 42];

    const int tid = threadIdx.x;
    const int lane = tid & 31;
    const int w = tid >> 5;
    const int lq = lane >> 2;
    const int l4 = lane & 3;
    constexpr int JT = NT / 16;             // n8-tiles per warp (warp n = NT/2)
    const int wm = (w >> 1) * 32;
    const int wn = (w & 1) * (NT / 2);

    const bool bldr = (NT == 128) || (tid < 128);
    const int ld_kk = (NT == 128) ? (tid >> 4) * 2 : ((tid & 127) >> 3) * 2;
    const int ld_nn = (NT == 128) ? (tid & 15) * 8 : (tid & 7) * 8;

#define CPA(st, k0)                                                               \
    do {                                                                          \
        const int r_ = tid >> 1;                                                  \
        const int c_ = (tid & 1) * 16;                                            \
        cp16(&As[st][r_ * 40 + c_], A + (size_t)(m0 + r_) * CC + (k0) + c_);      \
        cp16(&As[st][r_ * 40 + c_ + 8], A + (size_t)(m0 + r_) * CC + (k0) + c_ + 8); \
        asm volatile("cp.async.commit_group;" ::: "memory");                      \
    } while (0)

    float acc[2][JT][4];
#pragma unroll
    for (int i = 0; i < 2; i++)
#pragma unroll
        for (int j = 0; j < JT; j++)
#pragma unroll
            for (int r = 0; r < 4; r++) acc[i][j][r] = 0.f;

    uint4 bA, bB;
    CPA(0, 0);
    if (bldr) {
        bA = *(const uint4*)(Bp + (size_t)ld_kk * HW + n0 + ld_nn);
        bB = *(const uint4*)(Bp + (size_t)(ld_kk + 1) * HW + n0 + ld_nn);
    }

    for (int it = 0; it < 8; it++) {
        const int st = it & 1;
        if (bldr) {
            const __nv_bfloat16* pa = (const __nv_bfloat16*)&bA;
            const __nv_bfloat16* pb = (const __nv_bfloat16*)&bB;
#pragma unroll
            for (int j = 0; j < 8; j++) {
                __nv_bfloat162 t;
                t.x = pa[j]; t.y = pb[j];
                *(__nv_bfloat162*)&Bt[st][(ld_nn + j) * 42 + ld_kk] = t;
            }
        }
        asm volatile("cp.async.wait_group 0;" ::: "memory");
        __syncthreads();
        if (it < 7) {
            const int k1 = (it + 1) * 32;
            if (bldr) {
                bA = *(const uint4*)(Bp + (size_t)(k1 + ld_kk) * HW + n0 + ld_nn);
                bB = *(const uint4*)(Bp + (size_t)(k1 + ld_kk + 1) * HW + n0 + ld_nn);
            }
            CPA(st ^ 1, k1);
        }

#pragma unroll
        for (int ks = 0; ks < 2; ks++) {
            unsigned a[2][4];
#pragma unroll
            for (int i = 0; i < 2; i++) {
                const int r0 = (wm + i * 16 + lq) * 40 + ks * 16 + 2 * l4;
                const int r1 = (wm + i * 16 + lq + 8) * 40 + ks * 16 + 2 * l4;
                a[i][0] = *(const unsigned*)&As[st][r0];
                a[i][1] = *(const unsigned*)&As[st][r1];
                a[i][2] = *(const unsigned*)&As[st][r0 + 8];
                a[i][3] = *(const unsigned*)&As[st][r1 + 8];
            }
#pragma unroll
            for (int j = 0; j < JT; j++) {
                const int rb = (wn + j * 8 + lq) * 42 + ks * 16 + 2 * l4;
                unsigned b0 = *(const unsigned*)&Bt[st][rb];
                unsigned b1 = *(const unsigned*)&Bt[st][rb + 8];
#pragma unroll
                for (int i = 0; i < 2; i++)
                    mma_bf16(acc[i][j], a[i][0], a[i][1], a[i][2], a[i][3], b0, b1);
            }
        }
    }

#pragma unroll
    for (int i = 0; i < 2; i++) {
        const int m_lo = m0 + wm + i * 16 + lq;
        const int m_hi = m_lo + 8;
        const float b_lo = bias[m_lo], b_hi = bias[m_hi];
#pragma unroll
        for (int j = 0; j < JT; j++) {
            const int n = n0 + wn + j * 8 + 2 * l4;
            float v0 = acc[i][j][0] + b_lo;
            float v1 = acc[i][j][1] + b_lo;
            float v2 = acc[i][j][2] + b_hi;
            float v3 = acc[i][j][3] + b_hi;
            if (RESID) {
                float2 r0 = *(const float2*)(Rp + (size_t)m_lo * HW + n);
                float2 r1 = *(const float2*)(Rp + (size_t)m_hi * HW + n);
                v0 += r0.x; v1 += r0.y; v2 += r1.x; v3 += r1.y;
            }
            if (OBF16) {
                __nv_bfloat16* Cb = (__nv_bfloat16*)Cout_v + (size_t)bb * M_TOTAL * HW;
                *(unsigned*)(Cb + (size_t)m_lo * HW + n) = pack_bf16(v0, v1);
                *(unsigned*)(Cb + (size_t)m_hi * HW + n) = pack_bf16(v2, v3);
            } else {
                float* Cf = (float*)Cout_v + (size_t)bb * M_TOTAL * HW;
                float2 s0 = {v0, v1}, s1 = {v2, v3};
                *(float2*)(Cf + (size_t)m_lo * HW + n) = s0;
                *(float2*)(Cf + (size_t)m_hi * HW + n) = s1;
            }
        }
    }
#undef CPA
}

// ---------------------------------------------------------------------------
// Kernel 3: bf16 flash attention. Qs/Of share one smem buffer (disjoint
// lifetimes: Qs dead after pre-loop fragment load; Of born after post-loop
// barrier). smem 35.3KB -> 4 blocks/SM with __launch_bounds__(256,4).
// ---------------------------------------------------------------------------
__global__ __launch_bounds__(256, 4) void attn_bf16() {
    const int qt = blockIdx.x & 7;
    const int bh = blockIdx.x >> 3;
    const int b = bh >> 3;
    const int h = bh & 7;
    const int n0q = qt * 128;

    const int tid = threadIdx.x;
    const int lane = tid & 31;
    const int w = tid >> 5;
    const int lq = lane >> 2;
    const int l4 = lane & 3;

    const __nv_bfloat16* base = g_qkvh + (size_t)b * 3 * CC * HW;
    const __nv_bfloat16* qp = base + (size_t)(h * HD) * HW;
    const __nv_bfloat16* kp = base + (size_t)(CC + h * HD) * HW;
    const __nv_bfloat16* vp = base + (size_t)(2 * CC + h * HD) * HW;

    __shared__ __align__(128) unsigned char QOf[32 * 132 * 4];  // 16896 B union
    __shared__ __align__(128) __nv_bfloat16 Ks[2][32][72];
    __shared__ __align__(128) __nv_bfloat16 Vs[2][32][72];
    __nv_bfloat16 (*Qs)[42] = (__nv_bfloat16 (*)[42])QOf;   // [128][42] (10752 B)
    float (*Of)[132] = (float (*)[132])QOf;                 // [32][132] (16896 B)

    const float qls = 0.17677669529663687f * 1.4426950408889634f;

    const int ld_d = tid >> 3;
    const int ld_kb = (tid & 7) * 8;

    cp16(&Ks[0][ld_d][ld_kb], kp + (size_t)ld_d * HW + ld_kb);
    cp16(&Vs[0][ld_d][ld_kb], vp + (size_t)ld_d * HW + ld_kb);
    asm volatile("cp.async.commit_group;" ::: "memory");

#pragma unroll
    for (int t = 0; t < 2; t++) {
        const int i = tid + t * 256;
        const int d = i >> 4, qb = (i & 15) * 8;
        uint4 v = *(const uint4*)(qp + (size_t)d * HW + n0q + qb);
        const __nv_bfloat16* pv = (const __nv_bfloat16*)&v;
#pragma unroll
        for (int j = 0; j < 8; j++)
            Qs[qb + j][d] = __float2bfloat16_rn(__bfloat162float(pv[j]) * qls);
    }
    __syncthreads();

    unsigned aQ[2][4];
    const int q0 = w * 16 + lq;
#pragma unroll
    for (int t = 0; t < 2; t++) {
        aQ[t][0] = *(const unsigned*)&Qs[q0][t * 16 + 2 * l4];
        aQ[t][1] = *(const unsigned*)&Qs[q0 + 8][t * 16 + 2 * l4];
        aQ[t][2] = *(const unsigned*)&Qs[q0][t * 16 + 2 * l4 + 8];
        aQ[t][3] = *(const unsigned*)&Qs[q0 + 8][t * 16 + 2 * l4 + 8];
    }
    // Qs is dead from here on; buffer reused as Of in the epilogue.

    const unsigned ks_base0 = (unsigned)__cvta_generic_to_shared(&Ks[0][0][0]);
    const unsigned vs_base0 = (unsigned)__cvta_generic_to_shared(&Vs[0][0][0]);
    const unsigned k_lrow = lane & 15;
    const unsigned k_lcol = (lane >> 4) * 8;
    const unsigned v_lrow = lane & 7;
    const unsigned v_lcol = (lane >> 3) * 8;

    float oacc[4][4];
#pragma unroll
    for (int j = 0; j < 4; j++)
#pragma unroll
        for (int r = 0; r < 4; r++) oacc[j][r] = 0.f;
    float l0run = 0.f, l1run = 0.f;

    for (int it = 0; it < 16; it++) {
        const int st = it & 1;
        asm volatile("cp.async.wait_group 0;" ::: "memory");
        __syncthreads();
        if (it < 15) {
            const int m1 = (it + 1) * 64;
            cp16(&Ks[st ^ 1][ld_d][ld_kb], kp + (size_t)ld_d * HW + m1 + ld_kb);
            cp16(&Vs[st ^ 1][ld_d][ld_kb], vp + (size_t)ld_d * HW + m1 + ld_kb);
            asm volatile("cp.async.commit_group;" ::: "memory");
        }
        const unsigned ks_b = ks_base0 + (unsigned)st * 32 * 72 * 2;
        const unsigned vs_b = vs_base0 + (unsigned)st * 32 * 72 * 2;

#pragma unroll
        for (int tp = 0; tp < 2; tp++) {
            float sc[4][4];
#pragma unroll
            for (int jpp = 0; jpp < 2; jpp++) {
                const int jp = 2 * tp + jpp;
                unsigned kb0[4], kb1[4];
                ldsm_x4_t(kb0[0], kb0[1], kb0[2], kb0[3],
                          ks_b + (k_lrow * 72 + jp * 16 + k_lcol) * 2);
                ldsm_x4_t(kb1[0], kb1[1], kb1[2], kb1[3],
                          ks_b + ((16 + k_lrow) * 72 + jp * 16 + k_lcol) * 2);
                mma_bf16_z(sc[2 * jpp], aQ[0][0], aQ[0][1], aQ[0][2], aQ[0][3], kb0[0], kb0[1]);
                mma_bf16(sc[2 * jpp], aQ[1][0], aQ[1][1], aQ[1][2], aQ[1][3], kb1[0], kb1[1]);
                mma_bf16_z(sc[2 * jpp + 1], aQ[0][0], aQ[0][1], aQ[0][2], aQ[0][3], kb0[2], kb0[3]);
                mma_bf16(sc[2 * jpp + 1], aQ[1][0], aQ[1][1], aQ[1][2], aQ[1][3], kb1[2], kb1[3]);
            }

            unsigned pa01[4], pa23[4];
#pragma unroll
            for (int j = 0; j < 4; j++) {
                const float p0 = ex2(sc[j][0]);
                const float p1 = ex2(sc[j][1]);
                const float p2 = ex2(sc[j][2]);
                const float p3 = ex2(sc[j][3]);
                l0run += p0 + p1;
                l1run += p2 + p3;
                pa01[j] = pack_bf16(p0, p1);
                pa23[j] = pack_bf16(p2, p3);
            }

            unsigned vb[4][4];
#pragma unroll
            for (int j = 0; j < 4; j++)
                ldsm_x4(vb[j][0], vb[j][1], vb[j][2], vb[j][3],
                        vs_b + ((j * 8 + v_lrow) * 72 + tp * 32 + v_lcol) * 2);
#pragma unroll
            for (int tt = 0; tt < 2; tt++) {
                const unsigned a0 = pa01[2 * tt];
                const unsigned a1 = pa23[2 * tt];
                const unsigned a2 = pa01[2 * tt + 1];
                const unsigned a3 = pa23[2 * tt + 1];
#pragma unroll
                for (int j = 0; j < 4; j++)
                    mma_bf16(oacc[j], a0, a1, a2, a3, vb[j][2 * tt], vb[j][2 * tt + 1]);
            }
        }
    }

    l0run += __shfl_xor_sync(0xffffffffu, l0run, 1);
    l0run += __shfl_xor_sync(0xffffffffu, l0run, 2);
    l1run += __shfl_xor_sync(0xffffffffu, l1run, 1);
    l1run += __shfl_xor_sync(0xffffffffu, l1run, 2);

    __syncthreads();
    const float inv0 = 1.f / l0run;
    const float inv1 = 1.f / l1run;
#pragma unroll
    for (int j = 0; j < 4; j++) {
        const int d = j * 8 + 2 * l4;
        Of[d][q0] = oacc[j][0] * inv0;
        Of[d + 1][q0] = oacc[j][1] * inv0;
        Of[d][q0 + 8] = oacc[j][2] * inv1;
        Of[d + 1][q0 + 8] = oacc[j][3] * inv1;
    }
    __syncthreads();

    __nv_bfloat16* aob = g_aoh + ((size_t)b * CC + h * HD) * HW;
#pragma unroll
    for (int t = 0; t < 4; t++) {
        const int i = tid + t * 256;
        const int d = i >> 5, q4 = (i & 31) * 4;
        float4 v = *(const float4*)&Of[d][q4];
        uint2 o; o.x = pack_bf16(v.x, v.y); o.y = pack_bf16(v.z, v.w);
        *(uint2*)(aob + (size_t)d * HW + n0q + q4) = o;
    }
}

// ---------------------------------------------------------------------------
extern "C" void kernel_launch(void* const* d_in, const int* in_sizes, int n_in,
                              void* d_out, int out_size) {
    const float* x = (const float*)d_in[0];
    const float* gn_scale = (const float*)d_in[1];
    const float* gn_bias = (const float*)d_in[2];
    const float* w_qkv = (const float*)d_in[3];
    const float* b_qkv = (const float*)d_in[4];
    const float* w_out = (const float*)d_in[5];
    const float* b_out = (const float*)d_in[6];
    float* out = (float*)d_out;

    __nv_bfloat16 *hh, *qkvh, *aoh, *wqh, *woh;
    cudaGetSymbolAddress((void**)&hh, g_hh);
    cudaGetSymbolAddress((void**)&qkvh, g_qkvh);
    cudaGetSymbolAddress((void**)&aoh, g_aoh);
    cudaGetSymbolAddress((void**)&wqh, g_wqh);
    cudaGetSymbolAddress((void**)&woh, g_woh);

    gn_wconv_kernel<<<BB * NG + 256, 256>>>(x, gn_scale, gn_bias, w_qkv, w_out);

    {
        dim3 grid(HW / 128, (3 * CC) / 128, BB);   // 8 x 6 x 8 = 384
        gemm_bf<128, 3 * CC, false, true><<<grid, 256>>>(wqh, b_qkv, hh, nullptr, qkvh);
    }

    attn_bf16<<<BB * HEADS * 8, 256>>>();

    {
        dim3 grid(HW / 64, CC / 128, BB);          // 16 x 2 x 8 = 256
        gemm_bf<64, CC, true, false><<<grid, 256>>>(woh, b_out, aoh, x, out);
    }
}

// round 17
// speedup vs baseline: 1.0591x; 1.0591x over previous
#include <cuda_runtime.h>
#include <cuda_fp16.h>

#define BB 8
#define CC 256
#define HW 1024
#define HEADS 8
#define HD 32
#define NG 8
#define GS 32

__device__ __align__(256) __half g_hh[BB * CC * HW];
__device__ __align__(256) __half g_qkvh[BB * 3 * CC * HW];
__device__ __align__(256) __half g_aoh[BB * CC * HW];
__device__ __align__(256) __half g_wqh[3 * CC * CC];
__device__ __align__(256) __half g_woh[CC * CC];
__device__ float g_mean[BB * NG];
__device__ float g_rstd[BB * NG];

// ---------------------------------------------------------------------------
__device__ __forceinline__ void mma_h(float c[4], unsigned a0, unsigned a1,
                                      unsigned a2, unsigned a3,
                                      unsigned b0, unsigned b1) {
    asm volatile(
        "mma.sync.aligned.m16n8k16.row.col.f32.f16.f16.f32 "
        "{%0,%1,%2,%3},{%4,%5,%6,%7},{%8,%9},{%0,%1,%2,%3};"
        : "+f"(c[0]), "+f"(c[1]), "+f"(c[2]), "+f"(c[3])
        : "r"(a0), "r"(a1), "r"(a2), "r"(a3), "r"(b0), "r"(b1));
}

__device__ __forceinline__ void mma_h_z(float c[4], unsigned a0, unsigned a1,
                                        unsigned a2, unsigned a3,
                                        unsigned b0, unsigned b1) {
    asm volatile(
        "mma.sync.aligned.m16n8k16.row.col.f32.f16.f16.f32 "
        "{%0,%1,%2,%3},{%4,%5,%6,%7},{%8,%9},{%10,%11,%12,%13};"
        : "=f"(c[0]), "=f"(c[1]), "=f"(c[2]), "=f"(c[3])
        : "r"(a0), "r"(a1), "r"(a2), "r"(a3), "r"(b0), "r"(b1),
          "f"(0.f), "f"(0.f), "f"(0.f), "f"(0.f));
}

__device__ __forceinline__ unsigned pack_f16(float lo, float hi) {
    __half2 t = __floats2half2_rn(lo, hi);
    return *(unsigned*)&t;
}

__device__ __forceinline__ unsigned ex2_h2(unsigned a) {
    unsigned r;
    asm("ex2.approx.f16x2 %0, %1;" : "=r"(r) : "r"(a));
    return r;
}

__device__ __forceinline__ unsigned hadd2(unsigned a, unsigned b) {
    unsigned r;
    asm("add.rn.f16x2 %0, %1, %2;" : "=r"(r) : "r"(a), "r"(b));
    return r;
}

__device__ __forceinline__ float2 h2_to_f2(unsigned u) {
    __half2 h = *(__half2*)&u;
    return __half22float2(h);
}

__device__ __forceinline__ void cp16(void* smem, const void* gmem) {
    unsigned s = (unsigned)__cvta_generic_to_shared(smem);
    asm volatile("cp.async.ca.shared.global [%0], [%1], 16;" :: "r"(s), "l"(gmem));
}

__device__ __forceinline__ void ldsm_x4(unsigned& r0, unsigned& r1, unsigned& r2,
                                        unsigned& r3, unsigned addr) {
    asm volatile("ldmatrix.sync.aligned.m8n8.x4.shared.b16 {%0,%1,%2,%3}, [%4];"
                 : "=r"(r0), "=r"(r1), "=r"(r2), "=r"(r3) : "r"(addr));
}

__device__ __forceinline__ void ldsm_x4_t(unsigned& r0, unsigned& r1, unsigned& r2,
                                          unsigned& r3, unsigned addr) {
    asm volatile("ldmatrix.sync.aligned.m8n8.x4.trans.shared.b16 {%0,%1,%2,%3}, [%4];"
                 : "=r"(r0), "=r"(r1), "=r"(r2), "=r"(r3) : "r"(addr));
}

// ---------------------------------------------------------------------------
// Kernel 1a: GN stats (blocks 0..63) + weight conversion (blocks 64..319)
// ---------------------------------------------------------------------------
__global__ __launch_bounds__(256) void gn_stats_wconv(const float* __restrict__ x,
                                                      const float* __restrict__ wq,
                                                      const float* __restrict__ wo) {
    if (blockIdx.x >= BB * NG) {
        const int i = (blockIdx.x - BB * NG) * 256 + threadIdx.x;
        if (i < 49152) {
            float4 v = ((const float4*)wq)[i];
            uint2 o; o.x = pack_f16(v.x, v.y); o.y = pack_f16(v.z, v.w);
            ((uint2*)g_wqh)[i] = o;
        } else {
            const int k = i - 49152;
            float4 v = ((const float4*)wo)[k];
            uint2 o; o.x = pack_f16(v.x, v.y); o.y = pack_f16(v.z, v.w);
            ((uint2*)g_woh)[k] = o;
        }
        return;
    }
    const int bg = blockIdx.x;
    const int NE = GS * HW;
    const float* xp = x + (size_t)bg * NE;

    float s = 0.f, s2 = 0.f;
    const float4* x4 = (const float4*)xp;
    for (int i = threadIdx.x; i < NE / 4; i += 256) {
        float4 v = x4[i];
        s += v.x + v.y + v.z + v.w;
        s2 += v.x * v.x + v.y * v.y + v.z * v.z + v.w * v.w;
    }
    __shared__ float rs[256], rs2[256];
    rs[threadIdx.x] = s; rs2[threadIdx.x] = s2;
    __syncthreads();
    for (int o = 128; o > 0; o >>= 1) {
        if (threadIdx.x < o) {
            rs[threadIdx.x] += rs[threadIdx.x + o];
            rs2[threadIdx.x] += rs2[threadIdx.x + o];
        }
        __syncthreads();
    }
    if (threadIdx.x == 0) {
        const float mean = rs[0] / NE;
        const float var = rs2[0] / NE - mean * mean;
        g_mean[bg] = mean;
        g_rstd[bg] = rsqrtf(var + 1e-5f);
    }
}

// ---------------------------------------------------------------------------
// Kernel 1b: GN apply -> f16 (256 blocks; 4 per (b,g))
// ---------------------------------------------------------------------------
__global__ __launch_bounds__(256) void gn_apply(const float* __restrict__ x,
                                                const float* __restrict__ sc,
                                                const float* __restrict__ bi) {
    const int bg = blockIdx.x >> 2;
    const int qtr = blockIdx.x & 3;
    const int g = bg % NG;
    const float mean = g_mean[bg];
    const float rstd = g_rstd[bg];

    const size_t base4 = (size_t)bg * 8192 + qtr * 2048;   // float4 units
    const float4* x4 = (const float4*)x + base4;
    uint2* h2 = (uint2*)g_hh + base4;

    for (int i = threadIdx.x; i < 2048; i += 256) {
        const int c = g * GS + ((qtr * 2048 + i) >> 8);    // 256 float4 per channel
        const float a = sc[c] * rstd;
        const float d = bi[c] - mean * a;
        float4 v = x4[i];
        uint2 o;
        o.x = pack_f16(v.x * a + d, v.y * a + d);
        o.y = pack_f16(v.z * a + d, v.w * a + d);
        h2[i] = o;
    }
}

// ---------------------------------------------------------------------------
// Kernel 2/4: f16 m16n8k16 GEMM, 128x128 tile (validated R12/R15 structure)
// ---------------------------------------------------------------------------
template <int M_TOTAL, bool RESID, bool OH16>
__global__ __launch_bounds__(256, 2) void gemm_h(const __half* __restrict__ A,
                                                 const float* __restrict__ bias,
                                                 const __half* __restrict__ Bmat,
                                                 const float* __restrict__ resid,
                                                 void* __restrict__ Cout_v) {
    const int bb = blockIdx.z;
    const int m0 = blockIdx.y * 128;
    const int n0 = blockIdx.x * 128;
    const __half* Bp = Bmat + (size_t)bb * CC * HW;
    const float* Rp = RESID ? (resid + (size_t)bb * M_TOTAL * HW) : nullptr;

    __shared__ __align__(128) __half As[2][128 * 40];
    __shared__ __align__(128) __half Bt[2][128 * 42];

    const int tid = threadIdx.x;
    const int lane = tid & 31;
    const int w = tid >> 5;
    const int lq = lane >> 2;
    const int l4 = lane & 3;
    const int wm = (w >> 1) * 32;
    const int wn = (w & 1) * 64;

    const int ld_kk = (tid >> 4) * 2;
    const int ld_nn = (tid & 15) * 8;

#define CPA(st, k0)                                                               \
    do {                                                                          \
        const int r_ = tid >> 1;                                                  \
        const int c_ = (tid & 1) * 16;                                            \
        cp16(&As[st][r_ * 40 + c_], A + (size_t)(m0 + r_) * CC + (k0) + c_);      \
        cp16(&As[st][r_ * 40 + c_ + 8], A + (size_t)(m0 + r_) * CC + (k0) + c_ + 8); \
        asm volatile("cp.async.commit_group;" ::: "memory");                      \
    } while (0)

    float acc[2][8][4];
#pragma unroll
    for (int i = 0; i < 2; i++)
#pragma unroll
        for (int j = 0; j < 8; j++)
#pragma unroll
            for (int r = 0; r < 4; r++) acc[i][j][r] = 0.f;

    uint4 bA, bB;
    CPA(0, 0);
    bA = *(const uint4*)(Bp + (size_t)ld_kk * HW + n0 + ld_nn);
    bB = *(const uint4*)(Bp + (size_t)(ld_kk + 1) * HW + n0 + ld_nn);

    for (int it = 0; it < 8; it++) {
        const int st = it & 1;
        {
            const __half* pa = (const __half*)&bA;
            const __half* pb = (const __half*)&bB;
#pragma unroll
            for (int j = 0; j < 8; j++) {
                __half2 t;
                t.x = pa[j]; t.y = pb[j];
                *(__half2*)&Bt[st][(ld_nn + j) * 42 + ld_kk] = t;
            }
        }
        asm volatile("cp.async.wait_group 0;" ::: "memory");
        __syncthreads();
        if (it < 7) {
            const int k1 = (it + 1) * 32;
            bA = *(const uint4*)(Bp + (size_t)(k1 + ld_kk) * HW + n0 + ld_nn);
            bB = *(const uint4*)(Bp + (size_t)(k1 + ld_kk + 1) * HW + n0 + ld_nn);
            CPA(st ^ 1, k1);
        }

#pragma unroll
        for (int ks = 0; ks < 2; ks++) {
            unsigned a[2][4];
#pragma unroll
            for (int i = 0; i < 2; i++) {
                const int r0 = (wm + i * 16 + lq) * 40 + ks * 16 + 2 * l4;
                const int r1 = (wm + i * 16 + lq + 8) * 40 + ks * 16 + 2 * l4;
                a[i][0] = *(const unsigned*)&As[st][r0];
                a[i][1] = *(const unsigned*)&As[st][r1];
                a[i][2] = *(const unsigned*)&As[st][r0 + 8];
                a[i][3] = *(const unsigned*)&As[st][r1 + 8];
            }
#pragma unroll
            for (int j = 0; j < 8; j++) {
                const int rb = (wn + j * 8 + lq) * 42 + ks * 16 + 2 * l4;
                unsigned b0 = *(const unsigned*)&Bt[st][rb];
                unsigned b1 = *(const unsigned*)&Bt[st][rb + 8];
#pragma unroll
                for (int i = 0; i < 2; i++)
                    mma_h(acc[i][j], a[i][0], a[i][1], a[i][2], a[i][3], b0, b1);
            }
        }
    }

#pragma unroll
    for (int i = 0; i < 2; i++) {
        const int m_lo = m0 + wm + i * 16 + lq;
        const int m_hi = m_lo + 8;
        const float b_lo = bias[m_lo], b_hi = bias[m_hi];
#pragma unroll
        for (int j = 0; j < 8; j++) {
            const int n = n0 + wn + j * 8 + 2 * l4;
            float v0 = acc[i][j][0] + b_lo;
            float v1 = acc[i][j][1] + b_lo;
            float v2 = acc[i][j][2] + b_hi;
            float v3 = acc[i][j][3] + b_hi;
            if (RESID) {
                float2 r0 = *(const float2*)(Rp + (size_t)m_lo * HW + n);
                float2 r1 = *(const float2*)(Rp + (size_t)m_hi * HW + n);
                v0 += r0.x; v1 += r0.y; v2 += r1.x; v3 += r1.y;
            }
            if (OH16) {
                __half* Cb = (__half*)Cout_v + (size_t)bb * M_TOTAL * HW;
                *(unsigned*)(Cb + (size_t)m_lo * HW + n) = pack_f16(v0, v1);
                *(unsigned*)(Cb + (size_t)m_hi * HW + n) = pack_f16(v2, v3);
            } else {
                float* Cf = (float*)Cout_v + (size_t)bb * M_TOTAL * HW;
                float2 s0 = {v0, v1}, s1 = {v2, v3};
                *(float2*)(Cf + (size_t)m_lo * HW + n) = s0;
                *(float2*)(Cf + (size_t)m_hi * HW + n) = s1;
            }
        }
    }
#undef CPA
}

// ---------------------------------------------------------------------------
// Kernel 3: f16 flash attention. ex2.approx.f16x2 computes exp pairs already
// packed as MMA A-fragments; l via HADD2 per 32-key block, folded to fp32.
// Qs/Of union smem; 4 blocks/SM.
// ---------------------------------------------------------------------------
__global__ __launch_bounds__(256, 4) void attn_h() {
    const int qt = blockIdx.x & 7;
    const int bh = blockIdx.x >> 3;
    const int b = bh >> 3;
    const int h = bh & 7;
    const int n0q = qt * 128;

    const int tid = threadIdx.x;
    const int lane = tid & 31;
    const int w = tid >> 5;
    const int lq = lane >> 2;
    const int l4 = lane & 3;

    const __half* base = g_qkvh + (size_t)b * 3 * CC * HW;
    const __half* qp = base + (size_t)(h * HD) * HW;
    const __half* kp = base + (size_t)(CC + h * HD) * HW;
    const __half* vp = base + (size_t)(2 * CC + h * HD) * HW;

    __shared__ __align__(128) unsigned char QOf[32 * 132 * 4];
    __shared__ __align__(128) __half Ks[2][32][72];
    __shared__ __align__(128) __half Vs[2][32][72];
    __half (*Qs)[42] = (__half (*)[42])QOf;
    float (*Of)[132] = (float (*)[132])QOf;

    const float qls = 0.17677669529663687f * 1.4426950408889634f;

    const int ld_d = tid >> 3;
    const int ld_kb = (tid & 7) * 8;

    cp16(&Ks[0][ld_d][ld_kb], kp + (size_t)ld_d * HW + ld_kb);
    cp16(&Vs[0][ld_d][ld_kb], vp + (size_t)ld_d * HW + ld_kb);
    asm volatile("cp.async.commit_group;" ::: "memory");

#pragma unroll
    for (int t = 0; t < 2; t++) {
        const int i = tid + t * 256;
        const int d = i >> 4, qb = (i & 15) * 8;
        uint4 v = *(const uint4*)(qp + (size_t)d * HW + n0q + qb);
        const __half* pv = (const __half*)&v;
#pragma unroll
        for (int j = 0; j < 8; j++)
            Qs[qb + j][d] = __float2half_rn(__half2float(pv[j]) * qls);
    }
    __syncthreads();

    unsigned aQ[2][4];
    const int q0 = w * 16 + lq;
#pragma unroll
    for (int t = 0; t < 2; t++) {
        aQ[t][0] = *(const unsigned*)&Qs[q0][t * 16 + 2 * l4];
        aQ[t][1] = *(const unsigned*)&Qs[q0 + 8][t * 16 + 2 * l4];
        aQ[t][2] = *(const unsigned*)&Qs[q0][t * 16 + 2 * l4 + 8];
        aQ[t][3] = *(const unsigned*)&Qs[q0 + 8][t * 16 + 2 * l4 + 8];
    }
    // Qs dead from here; buffer reused as Of.

    const unsigned ks_base0 = (unsigned)__cvta_generic_to_shared(&Ks[0][0][0]);
    const unsigned vs_base0 = (unsigned)__cvta_generic_to_shared(&Vs[0][0][0]);
    const unsigned k_lrow = lane & 15;
    const unsigned k_lcol = (lane >> 4) * 8;
    const unsigned v_lrow = lane & 7;
    const unsigned v_lcol = (lane >> 3) * 8;

    float oacc[4][4];
#pragma unroll
    for (int j = 0; j < 4; j++)
#pragma unroll
        for (int r = 0; r < 4; r++) oacc[j][r] = 0.f;
    float l0run = 0.f, l1run = 0.f;

    for (int it = 0; it < 16; it++) {
        const int st = it & 1;
        asm volatile("cp.async.wait_group 0;" ::: "memory");
        __syncthreads();
        if (it < 15) {
            const int m1 = (it + 1) * 64;
            cp16(&Ks[st ^ 1][ld_d][ld_kb], kp + (size_t)ld_d * HW + m1 + ld_kb);
            cp16(&Vs[st ^ 1][ld_d][ld_kb], vp + (size_t)ld_d * HW + m1 + ld_kb);
            asm volatile("cp.async.commit_group;" ::: "memory");
        }
        const unsigned ks_b = ks_base0 + (unsigned)st * 32 * 72 * 2;
        const unsigned vs_b = vs_base0 + (unsigned)st * 32 * 72 * 2;

#pragma unroll
        for (int tp = 0; tp < 2; tp++) {
            float sc[4][4];
#pragma unroll
            for (int jpp = 0; jpp < 2; jpp++) {
                const int jp = 2 * tp + jpp;
                unsigned kb0[4], kb1[4];
                ldsm_x4_t(kb0[0], kb0[1], kb0[2], kb0[3],
                          ks_b + (k_lrow * 72 + jp * 16 + k_lcol) * 2);
                ldsm_x4_t(kb1[0], kb1[1], kb1[2], kb1[3],
                          ks_b + ((16 + k_lrow) * 72 + jp * 16 + k_lcol) * 2);
                mma_h_z(sc[2 * jpp], aQ[0][0], aQ[0][1], aQ[0][2], aQ[0][3], kb0[0], kb0[1]);
                mma_h(sc[2 * jpp], aQ[1][0], aQ[1][1], aQ[1][2], aQ[1][3], kb1[0], kb1[1]);
                mma_h_z(sc[2 * jpp + 1], aQ[0][0], aQ[0][1], aQ[0][2], aQ[0][3], kb0[2], kb0[3]);
                mma_h(sc[2 * jpp + 1], aQ[1][0], aQ[1][1], aQ[1][2], aQ[1][3], kb1[2], kb1[3]);
            }

            // p = 2^s computed two-at-a-time, already packed for the PV MMA
            unsigned pa01[4], pa23[4];
            unsigned lacc01 = 0u, lacc23 = 0u;
#pragma unroll
            for (int j = 0; j < 4; j++) {
                pa01[j] = ex2_h2(pack_f16(sc[j][0], sc[j][1]));
                pa23[j] = ex2_h2(pack_f16(sc[j][2], sc[j][3]));
                lacc01 = hadd2(lacc01, pa01[j]);
                lacc23 = hadd2(lacc23, pa23[j]);
            }
            {
                float2 t01 = h2_to_f2(lacc01);
                l0run += t01.x + t01.y;
                float2 t23 = h2_to_f2(lacc23);
                l1run += t23.x + t23.y;
            }

            unsigned vb[4][4];
#pragma unroll
            for (int j = 0; j < 4; j++)
                ldsm_x4(vb[j][0], vb[j][1], vb[j][2], vb[j][3],
                        vs_b + ((j * 8 + v_lrow) * 72 + tp * 32 + v_lcol) * 2);
#pragma unroll
            for (int tt = 0; tt < 2; tt++) {
                const unsigned a0 = pa01[2 * tt];
                const unsigned a1 = pa23[2 * tt];
                const unsigned a2 = pa01[2 * tt + 1];
                const unsigned a3 = pa23[2 * tt + 1];
#pragma unroll
                for (int j = 0; j < 4; j++)
                    mma_h(oacc[j], a0, a1, a2, a3, vb[j][2 * tt], vb[j][2 * tt + 1]);
            }
        }
    }

    l0run += __shfl_xor_sync(0xffffffffu, l0run, 1);
    l0run += __shfl_xor_sync(0xffffffffu, l0run, 2);
    l1run += __shfl_xor_sync(0xffffffffu, l1run, 1);
    l1run += __shfl_xor_sync(0xffffffffu, l1run, 2);

    __syncthreads();
    const float inv0 = 1.f / l0run;
    const float inv1 = 1.f / l1run;
#pragma unroll
    for (int j = 0; j < 4; j++) {
        const int d = j * 8 + 2 * l4;
        Of[d][q0] = oacc[j][0] * inv0;
        Of[d + 1][q0] = oacc[j][1] * inv0;
        Of[d][q0 + 8] = oacc[j][2] * inv1;
        Of[d + 1][q0 + 8] = oacc[j][3] * inv1;
    }
    __syncthreads();

    __half* aob = g_aoh + ((size_t)b * CC + h * HD) * HW;
#pragma unroll
    for (int t = 0; t < 4; t++) {
        const int i = tid + t * 256;
        const int d = i >> 5, q4 = (i & 31) * 4;
        float4 v = *(const float4*)&Of[d][q4];
        uint2 o; o.x = pack_f16(v.x, v.y); o.y = pack_f16(v.z, v.w);
        *(uint2*)(aob + (size_t)d * HW + n0q + q4) = o;
    }
}

// ---------------------------------------------------------------------------
extern "C" void kernel_launch(void* const* d_in, const int* in_sizes, int n_in,
                              void* d_out, int out_size) {
    const float* x = (const float*)d_in[0];
    const float* gn_scale = (const float*)d_in[1];
    const float* gn_bias = (const float*)d_in[2];
    const float* w_qkv = (const float*)d_in[3];
    const float* b_qkv = (const float*)d_in[4];
    const float* w_out = (const float*)d_in[5];
    const float* b_out = (const float*)d_in[6];
    float* out = (float*)d_out;

    __half *hh, *qkvh, *aoh, *wqh, *woh;
    cudaGetSymbolAddress((void**)&hh, g_hh);
    cudaGetSymbolAddress((void**)&qkvh, g_qkvh);
    cudaGetSymbolAddress((void**)&aoh, g_aoh);
    cudaGetSymbolAddress((void**)&wqh, g_wqh);
    cudaGetSymbolAddress((void**)&woh, g_woh);

    gn_stats_wconv<<<BB * NG + 256, 256>>>(x, w_qkv, w_out);
    gn_apply<<<256, 256>>>(x, gn_scale, gn_bias);

    {
        dim3 grid(HW / 128, (3 * CC) / 128, BB);   // 8 x 6 x 8 = 384
        gemm_h<3 * CC, false, true><<<grid, 256>>>(wqh, b_qkv, hh, nullptr, qkvh);
    }

    attn_h<<<BB * HEADS * 8, 256>>>();

    {
        dim3 grid(HW / 128, CC / 128, BB);         // 8 x 2 x 8 = 128
        gemm_h<CC, true, false><<<grid, 256>>>(woh, b_out, aoh, x, out);
    }
}